// round 1
// baseline (speedup 1.0000x reference)
#include <cuda_runtime.h>
#include <math.h>

// ---------------- problem constants ----------------
constexpr int B_  = 8;
constexpr int S_  = 4096;
constexpr int D_  = 768;
constexpr int H_  = 12;
constexpr int Wd  = 128;     // window
constexpr int L_  = 2;
constexpr int V_  = 512;
constexpr int FF_ = 3072;
constexpr int DH  = 64;      // D_/H_
constexpr int NB  = S_ / Wd; // 32
constexpr int BSi = B_ * S_; // 32768

// ---------------- scratch (device globals; no allocation allowed) ----------------
__device__ float g_X  [(size_t)BSi * D_];
__device__ float g_Q  [(size_t)BSi * D_];
__device__ float g_K  [(size_t)BSi * D_];
__device__ float g_V  [(size_t)BSi * D_];
__device__ float g_ATT[(size_t)BSi * D_];
__device__ float g_T1 [(size_t)BSi * D_];
__device__ float g_H  [(size_t)BSi * FF_];

// ---------------- helpers ----------------
__device__ __forceinline__ float warp_sum(float v) {
    #pragma unroll
    for (int o = 16; o > 0; o >>= 1) v += __shfl_xor_sync(0xffffffffu, v, o);
    return v;
}
__device__ __forceinline__ float warp_max(float v) {
    #pragma unroll
    for (int o = 16; o > 0; o >>= 1) v = fmaxf(v, __shfl_xor_sync(0xffffffffu, v, o));
    return v;
}

// ---------------- embedding gather ----------------
__global__ void embed_kernel(const int* __restrict__ call,
                             const float* __restrict__ emb,
                             float* __restrict__ X)
{
    size_t row = blockIdx.x;
    int c = call[row];
    const float* src = emb + (size_t)c * D_;
    float* dst = X + row * D_;
    for (int d = threadIdx.x; d < D_; d += blockDim.x) dst[d] = src[d];
}

// ---------------- SGEMM: C[m,n] = (sum_k A[m,k]*B[n,k] + bias[n]) * alpha, opt ReLU ----
// A: [M,K] row-major, B: [N,K] row-major. M%128==0, N%128==0, K%8==0.
template<bool RELU>
__global__ void __launch_bounds__(256) gemm_nt_kernel(
    const float* __restrict__ A, const float* __restrict__ B,
    const float* __restrict__ bias, float* __restrict__ C,
    int M, int N, int K, float alpha)
{
    __shared__ float As[8][128];
    __shared__ float Bs[8][128];

    const int tid = threadIdx.x;
    const int br  = blockIdx.y;
    const int bc  = blockIdx.x;

    const int lrow = tid >> 1;        // 0..127
    const int lk   = (tid & 1) << 2;  // 0 or 4

    const float* Ap = A + (size_t)(br * 128 + lrow) * K + lk;
    const float* Bp = B + (size_t)(bc * 128 + lrow) * K + lk;

    const int ty = tid >> 4;  // 0..15
    const int tx = tid & 15;  // 0..15

    float acc[8][8];
    #pragma unroll
    for (int i = 0; i < 8; i++)
        #pragma unroll
        for (int j = 0; j < 8; j++) acc[i][j] = 0.f;

    for (int k0 = 0; k0 < K; k0 += 8) {
        float4 a4 = *(const float4*)(Ap + k0);
        float4 b4 = *(const float4*)(Bp + k0);
        __syncthreads();
        As[lk + 0][lrow] = a4.x; As[lk + 1][lrow] = a4.y;
        As[lk + 2][lrow] = a4.z; As[lk + 3][lrow] = a4.w;
        Bs[lk + 0][lrow] = b4.x; Bs[lk + 1][lrow] = b4.y;
        Bs[lk + 2][lrow] = b4.z; Bs[lk + 3][lrow] = b4.w;
        __syncthreads();

        #pragma unroll
        for (int kk = 0; kk < 8; kk++) {
            float ar[8], brr[8];
            *(float4*)&ar[0]  = *(const float4*)&As[kk][ty * 8];
            *(float4*)&ar[4]  = *(const float4*)&As[kk][ty * 8 + 4];
            *(float4*)&brr[0] = *(const float4*)&Bs[kk][tx * 8];
            *(float4*)&brr[4] = *(const float4*)&Bs[kk][tx * 8 + 4];
            #pragma unroll
            for (int i = 0; i < 8; i++)
                #pragma unroll
                for (int j = 0; j < 8; j++)
                    acc[i][j] = fmaf(ar[i], brr[j], acc[i][j]);
        }
    }

    #pragma unroll
    for (int i = 0; i < 8; i++) {
        size_t row = (size_t)(br * 128 + ty * 8 + i);
        #pragma unroll
        for (int j0 = 0; j0 < 8; j0 += 4) {
            int col = bc * 128 + tx * 8 + j0;
            float4 r;
            r.x = (acc[i][j0 + 0] + bias[col + 0]) * alpha;
            r.y = (acc[i][j0 + 1] + bias[col + 1]) * alpha;
            r.z = (acc[i][j0 + 2] + bias[col + 2]) * alpha;
            r.w = (acc[i][j0 + 3] + bias[col + 3]) * alpha;
            if (RELU) {
                r.x = fmaxf(r.x, 0.f); r.y = fmaxf(r.y, 0.f);
                r.z = fmaxf(r.z, 0.f); r.w = fmaxf(r.w, 0.f);
            }
            *(float4*)(C + row * N + col) = r;
        }
    }
}

// ---------------- fused residual add + LayerNorm ----------------
// out[row] = LN(x[row] + (a? a[row]:0)) * g + beta. Block = 256 threads, row = blockIdx.x.
__global__ void __launch_bounds__(256) add_ln_kernel(
    const float* __restrict__ x, const float* __restrict__ a,
    const float* __restrict__ g, const float* __restrict__ beta,
    float* __restrict__ out)
{
    __shared__ float red[8];
    const int row = blockIdx.x;
    const int tid = threadIdx.x;
    const int lane = tid & 31, wid = tid >> 5;

    const float* xr = x + (size_t)row * D_;
    const float* ar = a ? (a + (size_t)row * D_) : nullptr;

    float v[3];
    float s = 0.f;
    #pragma unroll
    for (int i = 0; i < 3; i++) {
        int c = tid + i * 256;
        float val = xr[c];
        if (ar) val += ar[c];
        v[i] = val;
        s += val;
    }
    s = warp_sum(s);
    if (lane == 0) red[wid] = s;
    __syncthreads();
    float tot = 0.f;
    #pragma unroll
    for (int w = 0; w < 8; w++) tot += red[w];
    float mean = tot * (1.f / (float)D_);

    float s2 = 0.f;
    #pragma unroll
    for (int i = 0; i < 3; i++) { float d = v[i] - mean; s2 += d * d; }
    s2 = warp_sum(s2);
    __syncthreads();
    if (lane == 0) red[wid] = s2;
    __syncthreads();
    float tot2 = 0.f;
    #pragma unroll
    for (int w = 0; w < 8; w++) tot2 += red[w];
    float rs = rsqrtf(tot2 * (1.f / (float)D_) + 1e-5f);

    float* orow = out + (size_t)row * D_;
    #pragma unroll
    for (int i = 0; i < 3; i++) {
        int c = tid + i * 256;
        orow[c] = (v[i] - mean) * rs * g[c] + beta[c];
    }
}

// ---------------- banded attention + global key column ----------------
// Q,K,V,O layout: [B,S,H,DH]. One block per (band-block n, head h, batch b); 128 threads,
// one query per thread, online softmax over [global key 0] + 384 band keys.
constexpr int SMEM_BAND = 385 * DH * 2 * (int)sizeof(float); // 197120 bytes

__global__ void __launch_bounds__(128) band_attn_kernel(
    const float* __restrict__ Q, const float* __restrict__ Kt,
    const float* __restrict__ Vt, float* __restrict__ O)
{
    extern __shared__ float sm[];
    float* Kb = sm;                 // [385][64]
    float* Vb = sm + 385 * DH;      // [385][64]

    const int n = blockIdx.x, h = blockIdx.y, b = blockIdx.z;
    const int tid = threadIdx.x;

    // stage band keys (rows 0..383) + global key 0 (row 384)
    for (int t = tid; t < 385 * 16; t += 128) {
        int jj = t >> 4;
        int c  = t & 15;
        int pos = (jj < 384) ? (n * Wd - Wd + jj) : 0;
        float4 kv = make_float4(0.f, 0.f, 0.f, 0.f);
        float4 vv = kv;
        if (pos >= 0 && pos < S_) {
            size_t base = (((size_t)b * S_ + pos) * H_ + h) * DH + c * 4;
            kv = *(const float4*)(Kt + base);
            vv = *(const float4*)(Vt + base);
        }
        *(float4*)(Kb + jj * DH + c * 4) = kv;
        *(float4*)(Vb + jj * DH + c * 4) = vv;
    }
    __syncthreads();

    const int i = tid;              // query index within block
    const int qpos = n * Wd + i;

    float q[DH];
    {
        const float* qp = Q + (((size_t)b * S_ + qpos) * H_ + h) * DH;
        #pragma unroll
        for (int c = 0; c < 16; c++) {
            float4 f = *(const float4*)(qp + c * 4);
            q[c * 4 + 0] = f.x; q[c * 4 + 1] = f.y;
            q[c * 4 + 2] = f.z; q[c * 4 + 3] = f.w;
        }
    }

    float m = -1e30f, ssum = 0.f;
    float acc[DH];
    #pragma unroll
    for (int d = 0; d < DH; d++) acc[d] = 0.f;

    auto process = [&](int jj, float bias) {
        float s0 = 0.f, s1 = 0.f, s2 = 0.f, s3 = 0.f;
        const float4* kr = (const float4*)(Kb + jj * DH);
        #pragma unroll
        for (int c = 0; c < 16; c++) {
            float4 f = kr[c];
            s0 = fmaf(q[c * 4 + 0], f.x, s0);
            s1 = fmaf(q[c * 4 + 1], f.y, s1);
            s2 = fmaf(q[c * 4 + 2], f.z, s2);
            s3 = fmaf(q[c * 4 + 3], f.w, s3);
        }
        float s = (s0 + s1) + (s2 + s3) + bias;
        if (s > m) {
            float corr = __expf(m - s);
            ssum *= corr;
            #pragma unroll
            for (int d = 0; d < DH; d++) acc[d] *= corr;
            m = s;
        }
        float p = __expf(s - m);
        ssum += p;
        const float4* vr = (const float4*)(Vb + jj * DH);
        #pragma unroll
        for (int c = 0; c < 16; c++) {
            float4 f = vr[c];
            acc[c * 4 + 0] = fmaf(p, f.x, acc[c * 4 + 0]);
            acc[c * 4 + 1] = fmaf(p, f.y, acc[c * 4 + 1]);
            acc[c * 4 + 2] = fmaf(p, f.z, acc[c * 4 + 2]);
            acc[c * 4 + 3] = fmaf(p, f.w, acc[c * 4 + 3]);
        }
    };

    // global key column first (no bias)
    process(384, 0.f);

    // band keys: allowed iff 0 <= jj - i <= 256, valid iff 0 <= pos < S
    for (int jj = 0; jj < 384; jj++) {
        int rel = jj - i;
        int pos = n * Wd - Wd + jj;
        if (rel < 0 || rel > 256 || pos < 0 || pos >= S_) continue;
        float bias = (pos == 0) ? -10000.f : 0.f;  // global key masked from band
        process(jj, bias);
    }

    float inv = 1.f / ssum;
    float* op = O + (((size_t)b * S_ + qpos) * H_ + h) * DH;
    #pragma unroll
    for (int c = 0; c < 16; c++) {
        float4 r;
        r.x = acc[c * 4 + 0] * inv; r.y = acc[c * 4 + 1] * inv;
        r.z = acc[c * 4 + 2] * inv; r.w = acc[c * 4 + 3] * inv;
        *(float4*)(op + c * 4) = r;
    }
}

// ---------------- full attention for the global query (s = 0) ----------------
// One block per (h, b), 128 threads. Overwrites O at s=0.
__global__ void __launch_bounds__(128) global_attn_kernel(
    const float* __restrict__ Q, const float* __restrict__ Kt,
    const float* __restrict__ Vt, float* __restrict__ O)
{
    __shared__ float qs[DH];
    __shared__ float sc[S_];
    __shared__ float red[4];
    __shared__ float ob[128];

    const int h = blockIdx.x, b = blockIdx.y;
    const int tid = threadIdx.x;
    const int lane = tid & 31, wid = tid >> 5;

    if (tid < DH) qs[tid] = Q[(((size_t)b * S_) * H_ + h) * DH + tid];
    __syncthreads();

    float lm = -1e30f;
    for (int s = tid; s < S_; s += 128) {
        const float* kp = Kt + (((size_t)b * S_ + s) * H_ + h) * DH;
        float d0 = 0.f, d1 = 0.f, d2 = 0.f, d3 = 0.f;
        #pragma unroll
        for (int c = 0; c < 16; c++) {
            d0 = fmaf(qs[c * 4 + 0], kp[c * 4 + 0], d0);
            d1 = fmaf(qs[c * 4 + 1], kp[c * 4 + 1], d1);
            d2 = fmaf(qs[c * 4 + 2], kp[c * 4 + 2], d2);
            d3 = fmaf(qs[c * 4 + 3], kp[c * 4 + 3], d3);
        }
        float sv = (d0 + d1) + (d2 + d3);
        sc[s] = sv;
        lm = fmaxf(lm, sv);
    }
    lm = warp_max(lm);
    if (lane == 0) red[wid] = lm;
    __syncthreads();
    float gm = fmaxf(fmaxf(red[0], red[1]), fmaxf(red[2], red[3]));

    float ls = 0.f;
    for (int s = tid; s < S_; s += 128) {
        float p = __expf(sc[s] - gm);
        sc[s] = p;
        ls += p;
    }
    ls = warp_sum(ls);
    __syncthreads();
    if (lane == 0) red[wid] = ls;
    __syncthreads();
    float gs = red[0] + red[1] + red[2] + red[3];

    const int d = tid & 63, half = tid >> 6;
    float acc = 0.f;
    const int s0 = half * (S_ / 2), s1 = s0 + (S_ / 2);
    for (int s = s0; s < s1; s++)
        acc = fmaf(sc[s], Vt[(((size_t)b * S_ + s) * H_ + h) * DH + d], acc);
    ob[tid] = acc;
    __syncthreads();
    if (tid < DH)
        O[(((size_t)b * S_) * H_ + h) * DH + tid] = (ob[tid] + ob[tid + 64]) / gs;
}

// ---------------- launcher ----------------
extern "C" void kernel_launch(void* const* d_in, const int* in_sizes, int n_in,
                              void* d_out, int out_size)
{
    const int* call = (const int*)d_in[0];

    // Locate 'emb' robustly (first input of size V*D); weights follow in signature order.
    int e = 9;
    for (int i = 0; i < n_in; i++) {
        if (in_sizes[i] == V_ * D_) { e = i; break; }
    }
    const float* emb   = (const float*)d_in[e + 0];
    const float* Wq    = (const float*)d_in[e + 1];
    const float* bq    = (const float*)d_in[e + 2];
    const float* Wk    = (const float*)d_in[e + 3];
    const float* bk    = (const float*)d_in[e + 4];
    const float* Wv    = (const float*)d_in[e + 5];
    const float* bv    = (const float*)d_in[e + 6];
    const float* Wo    = (const float*)d_in[e + 7];
    const float* bo    = (const float*)d_in[e + 8];
    const float* W1    = (const float*)d_in[e + 9];
    const float* b1    = (const float*)d_in[e + 10];
    const float* W2    = (const float*)d_in[e + 11];
    const float* b2    = (const float*)d_in[e + 12];
    const float* g1    = (const float*)d_in[e + 13];
    const float* beta1 = (const float*)d_in[e + 14];
    const float* g2    = (const float*)d_in[e + 15];
    const float* beta2 = (const float*)d_in[e + 16];
    const float* gf    = (const float*)d_in[e + 17];
    const float* betaf = (const float*)d_in[e + 18];
    const float* Wc    = (const float*)d_in[e + 19];
    const float* bc    = (const float*)d_in[e + 20];
    float* out = (float*)d_out;

    float *X, *Qb, *Kb, *Vb, *ATT, *T1, *Hh;
    cudaGetSymbolAddress((void**)&X,   g_X);
    cudaGetSymbolAddress((void**)&Qb,  g_Q);
    cudaGetSymbolAddress((void**)&Kb,  g_K);
    cudaGetSymbolAddress((void**)&Vb,  g_V);
    cudaGetSymbolAddress((void**)&ATT, g_ATT);
    cudaGetSymbolAddress((void**)&T1,  g_T1);
    cudaGetSymbolAddress((void**)&Hh,  g_H);

    cudaFuncSetAttribute(band_attn_kernel,
                         cudaFuncAttributeMaxDynamicSharedMemorySize, SMEM_BAND);

    // embedding
    embed_kernel<<<BSi, 256>>>(call, emb, X);

    const dim3 gProj(D_ / 128, BSi / 128);   // 6 x 256
    const dim3 gFF1 (FF_ / 128, BSi / 128);  // 24 x 256
    const dim3 gCls (V_ / 128, BSi / 128);   // 4 x 256
    const dim3 gAttn(NB, H_, B_);
    const dim3 gGlob(H_, B_);

    const size_t DD  = (size_t)D_ * D_;
    const size_t FD  = (size_t)FF_ * D_;

    for (int l = 0; l < L_; l++) {
        // projections (Q scaled by 1/sqrt(dh) = 0.125 after bias, as in reference)
        gemm_nt_kernel<false><<<gProj, 256>>>(X, Wq + l * DD, bq + l * D_, Qb, BSi, D_, D_, 0.125f);
        gemm_nt_kernel<false><<<gProj, 256>>>(X, Wk + l * DD, bk + l * D_, Kb, BSi, D_, D_, 1.f);
        gemm_nt_kernel<false><<<gProj, 256>>>(X, Wv + l * DD, bv + l * D_, Vb, BSi, D_, D_, 1.f);

        // banded attention, then overwrite global query row
        band_attn_kernel<<<gAttn, 128, SMEM_BAND>>>(Qb, Kb, Vb, ATT);
        global_attn_kernel<<<gGlob, 128>>>(Qb, Kb, Vb, ATT);

        // output projection + residual LN
        gemm_nt_kernel<false><<<gProj, 256>>>(ATT, Wo + l * DD, bo + l * D_, T1, BSi, D_, D_, 1.f);
        add_ln_kernel<<<BSi, 256>>>(X, T1, g1 + l * D_, beta1 + l * D_, X);

        // FFN + residual LN
        gemm_nt_kernel<true><<<gFF1, 256>>>(X, W1 + l * FD, b1 + l * FF_, Hh, BSi, FF_, D_, 1.f);
        gemm_nt_kernel<false><<<gProj, 256>>>(Hh, W2 + l * FD, b2 + l * D_, T1, BSi, D_, FF_, 1.f);
        add_ln_kernel<<<BSi, 256>>>(X, T1, g2 + l * D_, beta2 + l * D_, X);
    }

    // final LN + classifier
    add_ln_kernel<<<BSi, 256>>>(X, nullptr, gf, betaf, T1);
    gemm_nt_kernel<false><<<gCls, 256>>>(T1, Wc, bc, out, BSi, V_, D_, 1.f);
}

// round 3
// speedup vs baseline: 1.6406x; 1.6406x over previous
#include <cuda_runtime.h>
#include <math.h>
#include <stdint.h>

// ---------------- problem constants ----------------
constexpr int B_  = 8;
constexpr int S_  = 4096;
constexpr int D_  = 768;
constexpr int H_  = 12;
constexpr int Wd  = 128;     // window
constexpr int L_  = 2;
constexpr int V_  = 512;
constexpr int FF_ = 3072;
constexpr int DH  = 64;      // D_/H_
constexpr int NB  = S_ / Wd; // 32
constexpr int BSi = B_ * S_; // 32768

// ---------------- scratch (device globals; no allocation allowed) ----------------
__device__ float g_X  [(size_t)BSi * D_];
__device__ float g_Q  [(size_t)BSi * D_];
__device__ float g_K  [(size_t)BSi * D_];
__device__ float g_V  [(size_t)BSi * D_];
__device__ float g_ATT[(size_t)BSi * D_];
__device__ float g_T1 [(size_t)BSi * D_];
__device__ float g_H  [(size_t)BSi * FF_];

// ---------------- small helpers ----------------
__device__ __forceinline__ uint32_t smem_u32(const void* p) {
    uint32_t a;
    asm("{ .reg .u64 t; cvta.to.shared.u64 t, %1; cvt.u32.u64 %0, t; }" : "=r"(a) : "l"(p));
    return a;
}
__device__ __forceinline__ float warp_sum(float v) {
    #pragma unroll
    for (int o = 16; o > 0; o >>= 1) v += __shfl_xor_sync(0xffffffffu, v, o);
    return v;
}
__device__ __forceinline__ float warp_max(float v) {
    #pragma unroll
    for (int o = 16; o > 0; o >>= 1) v = fmaxf(v, __shfl_xor_sync(0xffffffffu, v, o));
    return v;
}
__device__ __forceinline__ uint32_t cvt_tf32(float f) {
    uint32_t u;
    asm("cvt.rna.tf32.f32 %0, %1;" : "=r"(u) : "f"(f));
    return u;
}
__device__ __forceinline__ void mma_tf32(float* c, const uint32_t* a, const uint32_t* b) {
    asm volatile(
        "mma.sync.aligned.m16n8k8.row.col.f32.tf32.tf32.f32 "
        "{%0,%1,%2,%3}, {%4,%5,%6,%7}, {%8,%9}, {%0,%1,%2,%3};"
        : "+f"(c[0]), "+f"(c[1]), "+f"(c[2]), "+f"(c[3])
        : "r"(a[0]), "r"(a[1]), "r"(a[2]), "r"(a[3]), "r"(b[0]), "r"(b[1]));
}
#define CP_ASYNC16(dst, src) \
    asm volatile("cp.async.cg.shared.global [%0], [%1], 16;" :: "r"(dst), "l"(src))
#define CP_COMMIT() asm volatile("cp.async.commit_group;" ::: "memory")

// ================= tf32 tensor-core GEMM =================
// C[m,n] = (sum_k A[m,k]*B[n,k] + bias[n]) * alpha, optional ReLU.
// A:[M,K] row-major, B:[N,K] row-major. M%128==0, N%128==0, K%32==0.
// Tile 128x128x32, 256 threads (8 warps, 2(m) x 4(n), warp tile 64x32),
// double-buffered cp.async staging. smem row stride 36 floats: conflict-free
// fragment loads ( (36*g + tig) % 32 = (4g + tig) % 32 all distinct ) and
// 144B rows keep cp.async 16B alignment.
constexpr int GSTRIDE   = 36;
constexpr int GBUF      = 128 * GSTRIDE;                 // floats per tile buffer
constexpr int GEMM_SMEM = 4 * GBUF * (int)sizeof(float); // 73728 bytes

template<bool RELU>
__global__ void __launch_bounds__(256) gemm_mma_kernel(
    const float* __restrict__ A, const float* __restrict__ Bw,
    const float* __restrict__ bias, float* __restrict__ C,
    int M, int N, int K, float alpha)
{
    extern __shared__ float sm[];
    float* As = sm;            // [2][128][36]
    float* Bs = sm + 2 * GBUF; // [2][128][36]

    const int tid  = threadIdx.x;
    const int wid  = tid >> 5, lane = tid & 31;
    const int g    = lane >> 2, tig = lane & 3;
    const int wm   = (wid & 1) * 64;      // warp m-offset
    const int wn   = (wid >> 1) * 32;     // warp n-offset
    const int tile_m = blockIdx.y * 128, tile_n = blockIdx.x * 128;

    float c[4][4][4];
    #pragma unroll
    for (int i = 0; i < 4; i++)
        #pragma unroll
        for (int j = 0; j < 4; j++)
            #pragma unroll
            for (int r = 0; r < 4; r++) c[i][j][r] = 0.f;

    // per-thread staging coordinates: 4 x 16B chunks per tile per operand
    const int row0 = tid >> 3;          // chunk row for i=0 (0..31)
    const int cib  = tid & 7;           // 16B chunk within 128B row

    auto loadTile = [&](int buf, int k0) {
        const float* Agp = A  + (size_t)(tile_m + row0) * K + k0 + cib * 4;
        const float* Bgp = Bw + (size_t)(tile_n + row0) * K + k0 + cib * 4;
        uint32_t da = smem_u32(As + buf * GBUF + row0 * GSTRIDE + cib * 4);
        uint32_t db = smem_u32(Bs + buf * GBUF + row0 * GSTRIDE + cib * 4);
        #pragma unroll
        for (int i = 0; i < 4; i++) {
            CP_ASYNC16(da + i * 32 * GSTRIDE * 4, Agp + (size_t)i * 32 * K);
            CP_ASYNC16(db + i * 32 * GSTRIDE * 4, Bgp + (size_t)i * 32 * K);
        }
        CP_COMMIT();
    };

    auto compute = [&](int buf) {
        const float* Ab = As + buf * GBUF;
        const float* Bb = Bs + buf * GBUF;
        #pragma unroll
        for (int k8 = 0; k8 < 4; k8++) {
            uint32_t af[4][4], bf[4][2];
            #pragma unroll
            for (int mm = 0; mm < 4; mm++) {
                const float* p = Ab + (wm + mm * 16 + g) * GSTRIDE + k8 * 8 + tig;
                af[mm][0] = cvt_tf32(p[0]);
                af[mm][1] = cvt_tf32(p[8 * GSTRIDE]);
                af[mm][2] = cvt_tf32(p[4]);
                af[mm][3] = cvt_tf32(p[8 * GSTRIDE + 4]);
            }
            #pragma unroll
            for (int nn = 0; nn < 4; nn++) {
                const float* p = Bb + (wn + nn * 8 + g) * GSTRIDE + k8 * 8 + tig;
                bf[nn][0] = cvt_tf32(p[0]);
                bf[nn][1] = cvt_tf32(p[4]);
            }
            #pragma unroll
            for (int mm = 0; mm < 4; mm++)
                #pragma unroll
                for (int nn = 0; nn < 4; nn++)
                    mma_tf32(c[mm][nn], af[mm], bf[nn]);
        }
    };

    const int NK = K / 32;
    loadTile(0, 0);
    for (int ks = 0; ks < NK; ks++) {
        if (ks + 1 < NK) {
            loadTile((ks + 1) & 1, (ks + 1) * 32);
            asm volatile("cp.async.wait_group 1;" ::: "memory");
        } else {
            asm volatile("cp.async.wait_group 0;" ::: "memory");
        }
        __syncthreads();
        compute(ks & 1);
        __syncthreads();
    }

    // epilogue
    #pragma unroll
    for (int mm = 0; mm < 4; mm++) {
        const int rbase = tile_m + wm + mm * 16 + g;
        #pragma unroll
        for (int nn = 0; nn < 4; nn++) {
            const int col = tile_n + wn + nn * 8 + 2 * tig;
            const float b0 = bias[col], b1 = bias[col + 1];
            float2 v0, v1;
            v0.x = (c[mm][nn][0] + b0) * alpha;
            v0.y = (c[mm][nn][1] + b1) * alpha;
            v1.x = (c[mm][nn][2] + b0) * alpha;
            v1.y = (c[mm][nn][3] + b1) * alpha;
            if (RELU) {
                v0.x = fmaxf(v0.x, 0.f); v0.y = fmaxf(v0.y, 0.f);
                v1.x = fmaxf(v1.x, 0.f); v1.y = fmaxf(v1.y, 0.f);
            }
            *(float2*)(C + (size_t)rbase * N + col)       = v0;
            *(float2*)(C + (size_t)(rbase + 8) * N + col) = v1;
        }
    }
}

// ================= embedding gather =================
__global__ void embed_kernel(const int* __restrict__ call,
                             const float* __restrict__ emb,
                             float* __restrict__ X)
{
    size_t row = blockIdx.x;
    int c = call[row];
    const float* src = emb + (size_t)c * D_;
    float* dst = X + row * D_;
    for (int d = threadIdx.x; d < D_; d += blockDim.x) dst[d] = src[d];
}

// ================= fused residual add + LayerNorm =================
__global__ void __launch_bounds__(256) add_ln_kernel(
    const float* __restrict__ x, const float* __restrict__ a,
    const float* __restrict__ g, const float* __restrict__ beta,
    float* __restrict__ out)
{
    __shared__ float red[8];
    const int row = blockIdx.x;
    const int tid = threadIdx.x;
    const int lane = tid & 31, wid = tid >> 5;
    const float* xr = x + (size_t)row * D_;
    const float* ar = a ? (a + (size_t)row * D_) : nullptr;
    float v[3];
    float s = 0.f;
    #pragma unroll
    for (int i = 0; i < 3; i++) {
        int c = tid + i * 256;
        float val = xr[c];
        if (ar) val += ar[c];
        v[i] = val;
        s += val;
    }
    s = warp_sum(s);
    if (lane == 0) red[wid] = s;
    __syncthreads();
    float tot = 0.f;
    #pragma unroll
    for (int w = 0; w < 8; w++) tot += red[w];
    float mean = tot * (1.f / (float)D_);
    float s2 = 0.f;
    #pragma unroll
    for (int i = 0; i < 3; i++) { float d = v[i] - mean; s2 += d * d; }
    s2 = warp_sum(s2);
    __syncthreads();
    if (lane == 0) red[wid] = s2;
    __syncthreads();
    float tot2 = 0.f;
    #pragma unroll
    for (int w = 0; w < 8; w++) tot2 += red[w];
    float rs = rsqrtf(tot2 * (1.f / (float)D_) + 1e-5f);
    float* orow = out + (size_t)row * D_;
    #pragma unroll
    for (int i = 0; i < 3; i++) {
        int c = tid + i * 256;
        orow[c] = (v[i] - mean) * rs * g[c] + beta[c];
    }
}

// ================= banded attention + global key column =================
constexpr int SMEM_BAND = 385 * DH * 2 * (int)sizeof(float);

__global__ void __launch_bounds__(128) band_attn_kernel(
    const float* __restrict__ Q, const float* __restrict__ Kt,
    const float* __restrict__ Vt, float* __restrict__ O)
{
    extern __shared__ float smb[];
    float* Kb = smb;
    float* Vb = smb + 385 * DH;
    const int n = blockIdx.x, h = blockIdx.y, b = blockIdx.z;
    const int tid = threadIdx.x;
    for (int t = tid; t < 385 * 16; t += 128) {
        int jj = t >> 4;
        int c  = t & 15;
        int pos = (jj < 384) ? (n * Wd - Wd + jj) : 0;
        float4 kv = make_float4(0.f, 0.f, 0.f, 0.f);
        float4 vv = kv;
        if (pos >= 0 && pos < S_) {
            size_t base = (((size_t)b * S_ + pos) * H_ + h) * DH + c * 4;
            kv = *(const float4*)(Kt + base);
            vv = *(const float4*)(Vt + base);
        }
        *(float4*)(Kb + jj * DH + c * 4) = kv;
        *(float4*)(Vb + jj * DH + c * 4) = vv;
    }
    __syncthreads();
    const int i = tid;
    const int qpos = n * Wd + i;
    float q[DH];
    {
        const float* qp = Q + (((size_t)b * S_ + qpos) * H_ + h) * DH;
        #pragma unroll
        for (int c = 0; c < 16; c++) {
            float4 f = *(const float4*)(qp + c * 4);
            q[c*4+0]=f.x; q[c*4+1]=f.y; q[c*4+2]=f.z; q[c*4+3]=f.w;
        }
    }
    float m = -1e30f, ssum = 0.f;
    float acc[DH];
    #pragma unroll
    for (int d = 0; d < DH; d++) acc[d] = 0.f;
    auto process = [&](int jj, float bias) {
        float s0=0.f, s1=0.f, s2=0.f, s3=0.f;
        const float4* kr = (const float4*)(Kb + jj * DH);
        #pragma unroll
        for (int c = 0; c < 16; c++) {
            float4 f = kr[c];
            s0 = fmaf(q[c*4+0], f.x, s0); s1 = fmaf(q[c*4+1], f.y, s1);
            s2 = fmaf(q[c*4+2], f.z, s2); s3 = fmaf(q[c*4+3], f.w, s3);
        }
        float s = (s0+s1)+(s2+s3) + bias;
        if (s > m) {
            float corr = __expf(m - s);
            ssum *= corr;
            #pragma unroll
            for (int d = 0; d < DH; d++) acc[d] *= corr;
            m = s;
        }
        float p = __expf(s - m);
        ssum += p;
        const float4* vr = (const float4*)(Vb + jj * DH);
        #pragma unroll
        for (int c = 0; c < 16; c++) {
            float4 f = vr[c];
            acc[c*4+0]=fmaf(p,f.x,acc[c*4+0]); acc[c*4+1]=fmaf(p,f.y,acc[c*4+1]);
            acc[c*4+2]=fmaf(p,f.z,acc[c*4+2]); acc[c*4+3]=fmaf(p,f.w,acc[c*4+3]);
        }
    };
    process(384, 0.f);
    for (int jj = 0; jj < 384; jj++) {
        int rel = jj - i;
        int pos = n * Wd - Wd + jj;
        if (rel < 0 || rel > 256 || pos < 0 || pos >= S_) continue;
        float bias = (pos == 0) ? -10000.f : 0.f;
        process(jj, bias);
    }
    float inv = 1.f / ssum;
    float* op = O + (((size_t)b * S_ + qpos) * H_ + h) * DH;
    #pragma unroll
    for (int c = 0; c < 16; c++) {
        float4 r;
        r.x = acc[c*4+0]*inv; r.y = acc[c*4+1]*inv;
        r.z = acc[c*4+2]*inv; r.w = acc[c*4+3]*inv;
        *(float4*)(op + c * 4) = r;
    }
}

// ================= full attention for the global query (s = 0) =================
__global__ void __launch_bounds__(128) global_attn_kernel(
    const float* __restrict__ Q, const float* __restrict__ Kt,
    const float* __restrict__ Vt, float* __restrict__ O)
{
    __shared__ float qs[DH];
    __shared__ float sc[S_];
    __shared__ float red[4];
    __shared__ float ob[128];
    const int h = blockIdx.x, b = blockIdx.y;
    const int tid = threadIdx.x;
    const int lane = tid & 31, wid = tid >> 5;
    if (tid < DH) qs[tid] = Q[(((size_t)b * S_) * H_ + h) * DH + tid];
    __syncthreads();
    float lm = -1e30f;
    for (int s = tid; s < S_; s += 128) {
        const float* kp = Kt + (((size_t)b * S_ + s) * H_ + h) * DH;
        float d0=0.f,d1=0.f,d2=0.f,d3=0.f;
        #pragma unroll
        for (int c = 0; c < 16; c++) {
            d0 = fmaf(qs[c*4+0], kp[c*4+0], d0); d1 = fmaf(qs[c*4+1], kp[c*4+1], d1);
            d2 = fmaf(qs[c*4+2], kp[c*4+2], d2); d3 = fmaf(qs[c*4+3], kp[c*4+3], d3);
        }
        float sv = (d0+d1)+(d2+d3);
        sc[s] = sv;
        lm = fmaxf(lm, sv);
    }
    lm = warp_max(lm);
    if (lane == 0) red[wid] = lm;
    __syncthreads();
    float gm = fmaxf(fmaxf(red[0], red[1]), fmaxf(red[2], red[3]));
    float ls = 0.f;
    for (int s = tid; s < S_; s += 128) {
        float p = __expf(sc[s] - gm);
        sc[s] = p;
        ls += p;
    }
    ls = warp_sum(ls);
    __syncthreads();
    if (lane == 0) red[wid] = ls;
    __syncthreads();
    float gs = red[0] + red[1] + red[2] + red[3];
    const int d = tid & 63, half = tid >> 6;
    float acc = 0.f;
    const int s0 = half * (S_ / 2), s1 = s0 + (S_ / 2);
    for (int s = s0; s < s1; s++)
        acc = fmaf(sc[s], Vt[(((size_t)b * S_ + s) * H_ + h) * DH + d], acc);
    ob[tid] = acc;
    __syncthreads();
    if (tid < DH)
        O[(((size_t)b * S_) * H_ + h) * DH + tid] = (ob[tid] + ob[tid + 64]) / gs;
}

// ================= host side =================
static void gemm(const float* A, const float* Bw, const float* bias, float* C,
                 int M, int N, int K, float alpha, bool relu)
{
    dim3 grid(N / 128, M / 128);
    if (relu) gemm_mma_kernel<true ><<<grid, 256, GEMM_SMEM>>>(A, Bw, bias, C, M, N, K, alpha);
    else      gemm_mma_kernel<false><<<grid, 256, GEMM_SMEM>>>(A, Bw, bias, C, M, N, K, alpha);
}

extern "C" void kernel_launch(void* const* d_in, const int* in_sizes, int n_in,
                              void* d_out, int out_size)
{
    const int* call = (const int*)d_in[0];

    int e = 9;
    for (int i = 0; i < n_in; i++) {
        if (in_sizes[i] == V_ * D_) { e = i; break; }
    }
    const float* emb   = (const float*)d_in[e + 0];
    const float* Wq    = (const float*)d_in[e + 1];
    const float* bq    = (const float*)d_in[e + 2];
    const float* Wk    = (const float*)d_in[e + 3];
    const float* bk    = (const float*)d_in[e + 4];
    const float* Wv    = (const float*)d_in[e + 5];
    const float* bv    = (const float*)d_in[e + 6];
    const float* Wo    = (const float*)d_in[e + 7];
    const float* bo    = (const float*)d_in[e + 8];
    const float* W1    = (const float*)d_in[e + 9];
    const float* b1    = (const float*)d_in[e + 10];
    const float* W2    = (const float*)d_in[e + 11];
    const float* b2    = (const float*)d_in[e + 12];
    const float* g1    = (const float*)d_in[e + 13];
    const float* beta1 = (const float*)d_in[e + 14];
    const float* g2    = (const float*)d_in[e + 15];
    const float* beta2 = (const float*)d_in[e + 16];
    const float* gf    = (const float*)d_in[e + 17];
    const float* betaf = (const float*)d_in[e + 18];
    const float* Wc    = (const float*)d_in[e + 19];
    const float* bc    = (const float*)d_in[e + 20];
    float* out = (float*)d_out;

    float *X, *Qb, *Kb, *Vb, *ATT, *T1, *Hh;
    cudaGetSymbolAddress((void**)&X,   g_X);
    cudaGetSymbolAddress((void**)&Qb,  g_Q);
    cudaGetSymbolAddress((void**)&Kb,  g_K);
    cudaGetSymbolAddress((void**)&Vb,  g_V);
    cudaGetSymbolAddress((void**)&ATT, g_ATT);
    cudaGetSymbolAddress((void**)&T1,  g_T1);
    cudaGetSymbolAddress((void**)&Hh,  g_H);

    cudaFuncSetAttribute(band_attn_kernel,
                         cudaFuncAttributeMaxDynamicSharedMemorySize, SMEM_BAND);
    cudaFuncSetAttribute(gemm_mma_kernel<false>,
                         cudaFuncAttributeMaxDynamicSharedMemorySize, GEMM_SMEM);
    cudaFuncSetAttribute(gemm_mma_kernel<true>,
                         cudaFuncAttributeMaxDynamicSharedMemorySize, GEMM_SMEM);

    embed_kernel<<<BSi, 256>>>(call, emb, X);

    const dim3 gAttn(NB, H_, B_);
    const dim3 gGlob(H_, B_);
    const size_t DD = (size_t)D_ * D_;
    const size_t FD = (size_t)FF_ * D_;

    for (int l = 0; l < L_; l++) {
        gemm(X, Wq + l * DD, bq + l * D_, Qb, BSi, D_, D_, 0.125f, false);
        gemm(X, Wk + l * DD, bk + l * D_, Kb, BSi, D_, D_, 1.f, false);
        gemm(X, Wv + l * DD, bv + l * D_, Vb, BSi, D_, D_, 1.f, false);

        band_attn_kernel<<<gAttn, 128, SMEM_BAND>>>(Qb, Kb, Vb, ATT);
        global_attn_kernel<<<gGlob, 128>>>(Qb, Kb, Vb, ATT);

        gemm(ATT, Wo + l * DD, bo + l * D_, T1, BSi, D_, D_, 1.f, false);
        add_ln_kernel<<<BSi, 256>>>(X, T1, g1 + l * D_, beta1 + l * D_, X);

        gemm(X, W1 + l * FD, b1 + l * FF_, Hh, BSi, FF_, D_, 1.f, true);
        gemm(Hh, W2 + l * FD, b2 + l * D_, T1, BSi, D_, FF_, 1.f, false);
        add_ln_kernel<<<BSi, 256>>>(X, T1, g2 + l * D_, beta2 + l * D_, X);
    }

    add_ln_kernel<<<BSi, 256>>>(X, nullptr, gf, betaf, T1);
    gemm(T1, Wc, bc, out, BSi, V_, D_, 1.f, false);
}